// round 1
// baseline (speedup 1.0000x reference)
#include <cuda_runtime.h>
#include <math.h>

#define B_   4
#define N_   4096
#define M_   8192
#define C_   256
#define K_   8
#define FF_  1024
#define NQ_  (B_ * N_)   /* 16384 query tokens  */
#define NM_  (B_ * M_)   /* 32768 kv tokens     */

// ---------------- scratch (allocation-free, __device__ globals) ----------------
__device__ float g_Xq [NQ_ * C_];
__device__ float g_Xkv[NM_ * C_];
__device__ float g_Qq [NQ_ * C_];
__device__ float g_Kq [NQ_ * C_];   // reused later for FFN output F
__device__ float g_Vq [NQ_ * C_];
__device__ float g_Kkv[NM_ * C_];
__device__ float g_Vkv[NM_ * C_];
__device__ float g_O  [NQ_ * C_];
__device__ float g_Y  [NQ_ * C_];
__device__ float g_Hid[NQ_ * FF_];
__device__ int   g_nidx[NQ_ * K_];

// ---------------- pos-encoding: X = feat + xyz @ Wpos + bpos ----------------
__global__ void posenc_kernel(const float* __restrict__ xyz,
                              const float* __restrict__ feat,
                              const float* __restrict__ Wpos,
                              const float* __restrict__ bpos,
                              float* __restrict__ X) {
    int row = blockIdx.x;
    int c   = threadIdx.x;
    float x = xyz[row * 3 + 0], y = xyz[row * 3 + 1], z = xyz[row * 3 + 2];
    X[(size_t)row * C_ + c] = feat[(size_t)row * C_ + c]
                            + x * Wpos[c] + y * Wpos[C_ + c] + z * Wpos[2 * C_ + c]
                            + bpos[c];
}

// ---------------- SGEMM: C[r,n] = sum_k A[r,k] B[k,n] + bias[n] (opt relu) -----
// BM=BN=128, BK=8, 256 threads, 8x8 per thread. All dims divide evenly here.
template <bool RELU>
__global__ __launch_bounds__(256)
void sgemm_bias(const float* __restrict__ A, const float* __restrict__ B,
                const float* __restrict__ bias, float* __restrict__ C,
                int K, int N) {
    __shared__ float As[8][128];
    __shared__ float Bs[8][128];
    int tid  = threadIdx.x;
    int row0 = blockIdx.y * 128;
    int col0 = blockIdx.x * 128;

    int arow = tid >> 1;          // 0..127
    int acol = (tid & 1) << 2;    // 0 or 4
    int brw  = tid >> 5;          // 0..7
    int bcl  = (tid & 31) << 2;   // 0..124
    int trow = (tid >> 4) << 3;   // 0..120
    int tcol = (tid & 15) << 3;   // 0..120

    float acc[8][8] = {};
    for (int k0 = 0; k0 < K; k0 += 8) {
        float4 a4 = *(const float4*)&A[(size_t)(row0 + arow) * K + k0 + acol];
        As[acol + 0][arow] = a4.x;
        As[acol + 1][arow] = a4.y;
        As[acol + 2][arow] = a4.z;
        As[acol + 3][arow] = a4.w;
        *(float4*)&Bs[brw][bcl] =
            *(const float4*)&B[(size_t)(k0 + brw) * N + col0 + bcl];
        __syncthreads();
#pragma unroll
        for (int kk = 0; kk < 8; kk++) {
            float ar[8], br[8];
#pragma unroll
            for (int i = 0; i < 8; i++) ar[i] = As[kk][trow + i];
#pragma unroll
            for (int j = 0; j < 8; j++) br[j] = Bs[kk][tcol + j];
#pragma unroll
            for (int i = 0; i < 8; i++)
#pragma unroll
                for (int j = 0; j < 8; j++)
                    acc[i][j] = fmaf(ar[i], br[j], acc[i][j]);
        }
        __syncthreads();
    }
#pragma unroll
    for (int i = 0; i < 8; i++) {
#pragma unroll
        for (int j = 0; j < 8; j++) {
            float v = acc[i][j] + bias[col0 + tcol + j];
            if (RELU) v = fmaxf(v, 0.f);
            C[(size_t)(row0 + trow + i) * N + col0 + tcol + j] = v;
        }
    }
}

// ---------------- radius-kNN: top-8 smallest d2 within R^2=0.04 ----------------
// 1 warp per query, 8 queries per block. SMEM tile of kv points shared by block.
#define TILE_ 1024
__global__ void knn_kernel(const float* __restrict__ q_xyz,
                           const float* __restrict__ kv_xyz,
                           const unsigned char* __restrict__ kv_pad,
                           int* __restrict__ nidx) {
    __shared__ float sx[TILE_], sy[TILE_], sz[TILE_], sn[TILE_];
    const float INF = __int_as_float(0x7f800000);
    int warp = threadIdx.x >> 5, lane = threadIdx.x & 31;
    int q = blockIdx.x * 8 + warp;
    int b = q >> 12;                     // q / 4096
    float qx = q_xyz[q * 3 + 0], qy = q_xyz[q * 3 + 1], qz = q_xyz[q * 3 + 2];
    float qn = qx * qx + qy * qy + qz * qz;

    float d8[8];
    int   i8[8];
#pragma unroll
    for (int i = 0; i < 8; i++) { d8[i] = INF; i8[i] = -1; }
    float worst = INF;

    for (int t0 = 0; t0 < M_; t0 += TILE_) {
        __syncthreads();
        for (int t = threadIdx.x; t < TILE_; t += blockDim.x) {
            size_t j = (size_t)b * M_ + t0 + t;
            float x = kv_xyz[j * 3 + 0];
            float y = kv_xyz[j * 3 + 1];
            float z = kv_xyz[j * 3 + 2];
            sx[t] = x; sy[t] = y; sz[t] = z;
            sn[t] = kv_pad[j] ? INF : (x * x + y * y + z * z);
        }
        __syncthreads();
        for (int t = lane; t < TILE_; t += 32) {
            float d2 = qn + sn[t] - 2.f * (qx * sx[t] + qy * sy[t] + qz * sz[t]);
            if (d2 <= 0.04f && d2 < worst) {
                int p = 7;
                while (p > 0 && d8[p - 1] > d2) {
                    d8[p] = d8[p - 1]; i8[p] = i8[p - 1]; p--;
                }
                d8[p] = d2; i8[p] = t0 + t;
                worst = d8[7];
            }
        }
    }

    // merge 32 sorted lists of 8 -> global 8 smallest via warp-argmin rounds
    int p = 0;
    for (int r = 0; r < 8; r++) {
        float dv = (p < 8) ? d8[p] : INF;
        int   iv = (p < 8) ? i8[p] : 0;
        unsigned db = __float_as_uint(fmaxf(dv, 0.f));
        unsigned long long key = ((unsigned long long)db << 32)
                               | ((unsigned)(iv & 0x1FFF) << 5) | (unsigned)lane;
#pragma unroll
        for (int o = 16; o; o >>= 1) {
            unsigned long long other = __shfl_xor_sync(0xffffffffu, key, o);
            key = (other < key) ? other : key;
        }
        bool valid = ((unsigned)(key >> 32)) < 0x7f800000u;
        int wlane  = (int)(key & 31u);
        if (valid && lane == wlane) p++;
        if (lane == 0) nidx[q * 8 + r] = valid ? (int)((key >> 5) & 0x1FFF) : -1;
    }
}

// ---------------- gather attention: 1 warp per query --------------------------
// lane L owns dims [8L, 8L+8) => head h = L/4; per-head dot reduced with xor 1,2.
__global__ void attn_kernel(const float* __restrict__ Qq,
                            const float* __restrict__ Kq,
                            const float* __restrict__ Vq,
                            const float* __restrict__ Kkv,
                            const float* __restrict__ Vkv,
                            const int* __restrict__ nidx,
                            float* __restrict__ O) {
    int warp = threadIdx.x >> 5, lane = threadIdx.x & 31;
    int q = blockIdx.x * 8 + warp;
    int b = q >> 12;
    const size_t off = (size_t)q * C_ + lane * 8;

    float4 qa = *(const float4*)&Qq[off];
    float4 qb = *(const float4*)&Qq[off + 4];
    float qr[8] = {qa.x, qa.y, qa.z, qa.w, qb.x, qb.y, qb.z, qb.w};

    int rid[8];
    int nt = 1;
#pragma unroll
    for (int j = 0; j < 8; j++) {
        rid[j] = nidx[q * 8 + j];
        if (rid[j] >= 0) nt++;
    }

    float sc[9];
#pragma unroll
    for (int j = 0; j < 9; j++) {
        if (j == 0 || j < nt) {
            const float* kr = (j == 0)
                ? &Kq[off]
                : &Kkv[((size_t)b * M_ + rid[j - 1]) * C_ + lane * 8];
            float4 ka = *(const float4*)kr;
            float4 kb = *(const float4*)(kr + 4);
            float s = qr[0] * ka.x + qr[1] * ka.y + qr[2] * ka.z + qr[3] * ka.w
                    + qr[4] * kb.x + qr[5] * kb.y + qr[6] * kb.z + qr[7] * kb.w;
            s += __shfl_xor_sync(0xffffffffu, s, 1);
            s += __shfl_xor_sync(0xffffffffu, s, 2);
            sc[j] = s * 0.17677669529663687f;   // 1/sqrt(32)
        } else {
            sc[j] = -__int_as_float(0x7f800000);
        }
    }

    float m = sc[0];
#pragma unroll
    for (int j = 1; j < 9; j++) m = fmaxf(m, sc[j]);
    float w[9], ssum = 0.f;
#pragma unroll
    for (int j = 0; j < 9; j++) {
        w[j] = (j == 0 || j < nt) ? expf(sc[j] - m) : 0.f;
        ssum += w[j];
    }
    float inv = 1.f / ssum;

    float o[8] = {0, 0, 0, 0, 0, 0, 0, 0};
#pragma unroll
    for (int j = 0; j < 9; j++) {
        if (j == 0 || j < nt) {
            const float* vr = (j == 0)
                ? &Vq[off]
                : &Vkv[((size_t)b * M_ + rid[j - 1]) * C_ + lane * 8];
            float4 va = *(const float4*)vr;
            float4 vb = *(const float4*)(vr + 4);
            float a = w[j] * inv;
            o[0] += a * va.x; o[1] += a * va.y; o[2] += a * va.z; o[3] += a * va.w;
            o[4] += a * vb.x; o[5] += a * vb.y; o[6] += a * vb.z; o[7] += a * vb.w;
        }
    }
    float4 oa = {o[0], o[1], o[2], o[3]};
    float4 ob = {o[4], o[5], o[6], o[7]};
    *(float4*)&O[off]     = oa;
    *(float4*)&O[off + 4] = ob;
}

// ---------------- residual + LayerNorm (+optional extra add) -------------------
// out = LN(A + Bv) * g + be  (+ addq)  ; 1 warp per 256-dim row
__global__ void ln_res_kernel(const float* __restrict__ A,
                              const float* __restrict__ Bv,
                              const float* __restrict__ g,
                              const float* __restrict__ be,
                              const float* __restrict__ addq,
                              float* __restrict__ out) {
    int warp = threadIdx.x >> 5, lane = threadIdx.x & 31;
    int row = blockIdx.x * 8 + warp;
    size_t off = (size_t)row * C_ + lane * 8;

    float v[8];
    float4 a0 = *(const float4*)&A[off],  a1 = *(const float4*)&A[off + 4];
    float4 b0 = *(const float4*)&Bv[off], b1 = *(const float4*)&Bv[off + 4];
    v[0] = a0.x + b0.x; v[1] = a0.y + b0.y; v[2] = a0.z + b0.z; v[3] = a0.w + b0.w;
    v[4] = a1.x + b1.x; v[5] = a1.y + b1.y; v[6] = a1.z + b1.z; v[7] = a1.w + b1.w;

    float s = 0.f;
#pragma unroll
    for (int d = 0; d < 8; d++) s += v[d];
#pragma unroll
    for (int o = 16; o; o >>= 1) s += __shfl_xor_sync(0xffffffffu, s, o);
    float mu = s * (1.f / 256.f);

    float s2 = 0.f;
#pragma unroll
    for (int d = 0; d < 8; d++) { float t = v[d] - mu; s2 += t * t; }
#pragma unroll
    for (int o = 16; o; o >>= 1) s2 += __shfl_xor_sync(0xffffffffu, s2, o);
    float var = s2 * (1.f / 256.f);
    float is  = rsqrtf(var + 1e-5f);

#pragma unroll
    for (int d = 0; d < 8; d++) {
        float r = (v[d] - mu) * is * g[lane * 8 + d] + be[lane * 8 + d];
        if (addq) r += addq[off + d];
        out[off + d] = r;
    }
}

// ---------------- launch --------------------------------------------------------
extern "C" void kernel_launch(void* const* d_in, const int* in_sizes, int n_in,
                              void* d_out, int out_size) {
    (void)in_sizes; (void)n_in; (void)out_size;
    const float* q_xyz   = (const float*)d_in[0];
    const float* q_feat  = (const float*)d_in[1];
    const float* kv_xyz  = (const float*)d_in[2];
    const float* kv_feat = (const float*)d_in[3];
    const unsigned char* kv_pad = (const unsigned char*)d_in[4];
    const float* Wpos  = (const float*)d_in[5];
    const float* bpos  = (const float*)d_in[6];
    const float* Wq    = (const float*)d_in[7];
    const float* bq    = (const float*)d_in[8];
    const float* Wk    = (const float*)d_in[9];
    const float* bk    = (const float*)d_in[10];
    const float* Wv    = (const float*)d_in[11];
    const float* bv    = (const float*)d_in[12];
    const float* Wo    = (const float*)d_in[13];
    const float* bo    = (const float*)d_in[14];
    const float* ln1_g = (const float*)d_in[15];
    const float* ln1_b = (const float*)d_in[16];
    const float* W1    = (const float*)d_in[17];
    const float* b1    = (const float*)d_in[18];
    const float* W2    = (const float*)d_in[19];
    const float* b2    = (const float*)d_in[20];
    const float* ln2_g = (const float*)d_in[21];
    const float* ln2_b = (const float*)d_in[22];
    float* out = (float*)d_out;

    float *Xq, *Xkv, *Qq, *Kq, *Vq, *Kkv, *Vkv, *O, *Y, *Hid;
    int* nidx;
    cudaGetSymbolAddress((void**)&Xq,  g_Xq);
    cudaGetSymbolAddress((void**)&Xkv, g_Xkv);
    cudaGetSymbolAddress((void**)&Qq,  g_Qq);
    cudaGetSymbolAddress((void**)&Kq,  g_Kq);
    cudaGetSymbolAddress((void**)&Vq,  g_Vq);
    cudaGetSymbolAddress((void**)&Kkv, g_Kkv);
    cudaGetSymbolAddress((void**)&Vkv, g_Vkv);
    cudaGetSymbolAddress((void**)&O,   g_O);
    cudaGetSymbolAddress((void**)&Y,   g_Y);
    cudaGetSymbolAddress((void**)&Hid, g_Hid);
    cudaGetSymbolAddress((void**)&nidx, g_nidx);

    // token embeddings (pos-enc)
    posenc_kernel<<<NQ_, 256>>>(q_xyz,  q_feat,  Wpos, bpos, Xq);
    posenc_kernel<<<NM_, 256>>>(kv_xyz, kv_feat, Wpos, bpos, Xkv);

    // radius-kNN (independent of GEMMs, same stream keeps ordering simple)
    knn_kernel<<<NQ_ / 8, 256>>>(q_xyz, kv_xyz, kv_pad, nidx);

    // projections
    dim3 g1(C_ / 128, NQ_ / 128);
    sgemm_bias<false><<<g1, 256>>>(Xq, Wq, bq, Qq, C_, C_);
    sgemm_bias<false><<<g1, 256>>>(Xq, Wk, bk, Kq, C_, C_);
    sgemm_bias<false><<<g1, 256>>>(Xq, Wv, bv, Vq, C_, C_);
    dim3 g2(C_ / 128, NM_ / 128);
    sgemm_bias<false><<<g2, 256>>>(Xkv, Wk, bk, Kkv, C_, C_);
    sgemm_bias<false><<<g2, 256>>>(Xkv, Wv, bv, Vkv, C_, C_);

    // gather attention (token-0 row only)
    attn_kernel<<<NQ_ / 8, 256>>>(Qq, Kq, Vq, Kkv, Vkv, nidx, O);

    // output projection (reuse Qq as O2), residual + LN1
    sgemm_bias<false><<<g1, 256>>>(O, Wo, bo, Qq, C_, C_);
    ln_res_kernel<<<NQ_ / 8, 256>>>(Xq, Qq, ln1_g, ln1_b, nullptr, Y);

    // FFN
    dim3 g3(FF_ / 128, NQ_ / 128);
    sgemm_bias<true><<<g3, 256>>>(Y, W1, b1, Hid, C_, FF_);
    dim3 g4(C_ / 128, NQ_ / 128);
    sgemm_bias<false><<<g4, 256>>>(Hid, W2, b2, Kq, FF_, C_);   // F -> reuse Kq

    // residual + LN2 + final q_feat add, straight into d_out
    ln_res_kernel<<<NQ_ / 8, 256>>>(Y, Kq, ln2_g, ln2_b, q_feat, out);
}

// round 3
// speedup vs baseline: 1.8225x; 1.8225x over previous
#include <cuda_runtime.h>
#include <cuda_bf16.h>
#include <math.h>
#include <cstdint>

#define B_   4
#define N_   4096
#define M_   8192
#define C_   256
#define K_   8
#define FF_  1024
#define NQ_  (B_ * N_)   /* 16384 query tokens  */
#define NM_  (B_ * M_)   /* 32768 kv tokens     */

// ================= scratch (allocation-free, __device__ globals) ================
__device__ float          g_Xq   [NQ_ * C_];
__device__ __nv_bfloat16  g_Xq_b [NQ_ * C_];
__device__ __nv_bfloat16  g_Xkv_b[NM_ * C_];
__device__ float          g_Qq   [NQ_ * C_];   // later reused as O2
__device__ float          g_Kq   [NQ_ * C_];   // later reused as FFN2 out
__device__ float          g_Vq   [NQ_ * C_];
__device__ float          g_Kkv  [NM_ * C_];
__device__ float          g_Vkv  [NM_ * C_];
__device__ __nv_bfloat16  g_O_b  [NQ_ * C_];
__device__ float          g_Y    [NQ_ * C_];
__device__ __nv_bfloat16  g_Y_b  [NQ_ * C_];
__device__ __nv_bfloat16  g_Hid_b[NQ_ * FF_];
__device__ int            g_nidx [NQ_ * K_];
__device__ __nv_bfloat16  g_WTq[C_ * C_], g_WTk[C_ * C_], g_WTv[C_ * C_], g_WTo[C_ * C_];
__device__ __nv_bfloat16  g_WT1[FF_ * C_], g_WT2[C_ * FF_];

__device__ __forceinline__ uint32_t smem_u32(const void* p) {
    uint32_t a;
    asm("{ .reg .u64 t; cvta.to.shared.u64 t, %1; cvt.u32.u64 %0, t; }" : "=r"(a) : "l"(p));
    return a;
}

// ================= weight transpose: WT[n*K+k] = bf16(W[k*N+n]) =================
__global__ void transpose_w(const float* __restrict__ W, __nv_bfloat16* __restrict__ WT,
                            int K, int N) {
    int idx = blockIdx.x * 256 + threadIdx.x;
    if (idx >= K * N) return;
    int k = idx / N, n = idx % N;
    WT[(size_t)n * K + k] = __float2bfloat16(W[idx]);
}

// ================= pos-encoding ================================================
__global__ void posenc_kernel(const float* __restrict__ xyz,
                              const float* __restrict__ feat,
                              const float* __restrict__ Wpos,
                              const float* __restrict__ bpos,
                              float* __restrict__ Xf,
                              __nv_bfloat16* __restrict__ Xb) {
    int row = blockIdx.x;
    int c   = threadIdx.x;
    float x = xyz[row * 3 + 0], y = xyz[row * 3 + 1], z = xyz[row * 3 + 2];
    float v = feat[(size_t)row * C_ + c]
            + x * Wpos[c] + y * Wpos[C_ + c] + z * Wpos[2 * C_ + c] + bpos[c];
    if (Xf) Xf[(size_t)row * C_ + c] = v;
    Xb[(size_t)row * C_ + c] = __float2bfloat16(v);
}

// ================= HMMA GEMM: Out = A(bf16,[M,K]) @ BT(bf16,[N,K])^T + bias =====
// MODE 0: fp32 out.  MODE 1: relu -> bf16 out.
// Block 128x128, 8 warps (2 x 4), warp tile 64x32, BK=32, cp.async double buffer.
#define SSTR 40   /* padded smem row stride in bf16 (80 B = 20 banks) */

__device__ __forceinline__ void ldm_x4(uint32_t* r, uint32_t addr) {
    asm volatile("ldmatrix.sync.aligned.m8n8.x4.shared.b16 {%0,%1,%2,%3}, [%4];"
                 : "=r"(r[0]), "=r"(r[1]), "=r"(r[2]), "=r"(r[3]) : "r"(addr));
}
__device__ __forceinline__ void mma_bf16(float* d, const uint32_t* a, const uint32_t* b) {
    asm volatile(
        "mma.sync.aligned.m16n8k16.row.col.f32.bf16.bf16.f32 "
        "{%0,%1,%2,%3}, {%4,%5,%6,%7}, {%8,%9}, {%0,%1,%2,%3};"
        : "+f"(d[0]), "+f"(d[1]), "+f"(d[2]), "+f"(d[3])
        : "r"(a[0]), "r"(a[1]), "r"(a[2]), "r"(a[3]), "r"(b[0]), "r"(b[1]));
}
__device__ __forceinline__ void cp16(uint32_t saddr, const void* gaddr) {
    asm volatile("cp.async.cg.shared.global [%0], [%1], 16;" :: "r"(saddr), "l"(gaddr));
}

template <int MODE>
__global__ __launch_bounds__(256, 1)
void gemm_hmma(const __nv_bfloat16* __restrict__ A,
               const __nv_bfloat16* __restrict__ BT,
               const float* __restrict__ bias,
               void* __restrict__ Out, int K, int N) {
    __shared__ __align__(16) __nv_bfloat16 sA[2][128 * SSTR];
    __shared__ __align__(16) __nv_bfloat16 sB[2][128 * SSTR];

    int tid  = threadIdx.x;
    int wid  = tid >> 5, lane = tid & 31;
    int row0 = blockIdx.y * 128;
    int col0 = blockIdx.x * 128;
    int wm   = (wid & 1) * 64;   // warp M origin within block
    int wn   = (wid >> 1) * 32;  // warp N origin within block

    uint32_t aA[2] = { smem_u32(&sA[0][0]), smem_u32(&sA[1][0]) };
    uint32_t aB[2] = { smem_u32(&sB[0][0]), smem_u32(&sB[1][0]) };

    // loader indices: 512 uint4 per tile (128 rows x 4 segs of 16B)
    int r0i = tid >> 2, s0 = (tid & 3) * 8;              // part 0
    int r1i = (tid + 256) >> 2, s1 = ((tid + 256) & 3) * 8;

    auto issue = [&](int buf, int kc0) {
        cp16(aA[buf] + (r0i * SSTR + s0) * 2, A  + (size_t)(row0 + r0i) * K + kc0 + s0);
        cp16(aA[buf] + (r1i * SSTR + s1) * 2, A  + (size_t)(row0 + r1i) * K + kc0 + s1);
        cp16(aB[buf] + (r0i * SSTR + s0) * 2, BT + (size_t)(col0 + r0i) * K + kc0 + s0);
        cp16(aB[buf] + (r1i * SSTR + s1) * 2, BT + (size_t)(col0 + r1i) * K + kc0 + s1);
        asm volatile("cp.async.commit_group;" ::: "memory");
    };

    float acc[4][4][4] = {};

    int nk = K >> 5;
    issue(0, 0);
    for (int i = 0; i < nk; i++) {
        if (i + 1 < nk) {
            issue((i + 1) & 1, (i + 1) << 5);
            asm volatile("cp.async.wait_group 1;" ::: "memory");
        } else {
            asm volatile("cp.async.wait_group 0;" ::: "memory");
        }
        __syncthreads();

        int buf = i & 1;
#pragma unroll
        for (int ks = 0; ks < 2; ks++) {
            uint32_t afr[4][4];
#pragma unroll
            for (int mt = 0; mt < 4; mt++) {
                uint32_t addr = aA[buf]
                    + ((wm + mt * 16 + (lane & 15)) * SSTR
                       + ks * 16 + ((lane >> 4) << 3)) * 2;
                ldm_x4(afr[mt], addr);
            }
            uint32_t bfr[2][4];
#pragma unroll
            for (int np = 0; np < 2; np++) {
                uint32_t row = wn + np * 16 + ((lane >> 4) << 3) + (lane & 7);
                uint32_t kc  = ks * 16 + ((lane >> 3) & 1) * 8;
                ldm_x4(bfr[np], aB[buf] + (row * SSTR + kc) * 2);
            }
#pragma unroll
            for (int mt = 0; mt < 4; mt++)
#pragma unroll
                for (int nt = 0; nt < 4; nt++)
                    mma_bf16(acc[mt][nt], afr[mt], &bfr[nt >> 1][(nt & 1) * 2]);
        }
        __syncthreads();
    }

    // epilogue
    int g  = lane >> 2;
    int t2 = (lane & 3) * 2;
#pragma unroll
    for (int mt = 0; mt < 4; mt++) {
#pragma unroll
        for (int nt = 0; nt < 4; nt++) {
            int row = row0 + wm + mt * 16 + g;
            int col = col0 + wn + nt * 8 + t2;
            float2 b2 = *(const float2*)&bias[col];
            float v0 = acc[mt][nt][0] + b2.x, v1 = acc[mt][nt][1] + b2.y;
            float v2 = acc[mt][nt][2] + b2.x, v3 = acc[mt][nt][3] + b2.y;
            if (MODE == 0) {
                float* op = (float*)Out;
                *(float2*)&op[(size_t)row * N + col]       = make_float2(v0, v1);
                *(float2*)&op[(size_t)(row + 8) * N + col] = make_float2(v2, v3);
            } else {
                __nv_bfloat16* op = (__nv_bfloat16*)Out;
                __nv_bfloat162 p0 = __floats2bfloat162_rn(fmaxf(v0, 0.f), fmaxf(v1, 0.f));
                __nv_bfloat162 p1 = __floats2bfloat162_rn(fmaxf(v2, 0.f), fmaxf(v3, 0.f));
                *(__nv_bfloat162*)&op[(size_t)row * N + col]       = p0;
                *(__nv_bfloat162*)&op[(size_t)(row + 8) * N + col] = p1;
            }
        }
    }
}

// ================= radius-kNN (fp32) ============================================
#define TILE_ 1024
__global__ void knn_kernel(const float* __restrict__ q_xyz,
                           const float* __restrict__ kv_xyz,
                           const unsigned char* __restrict__ kv_pad,
                           int* __restrict__ nidx) {
    __shared__ float sx[TILE_], sy[TILE_], sz[TILE_], sn[TILE_];
    const float INF = __int_as_float(0x7f800000);
    int warp = threadIdx.x >> 5, lane = threadIdx.x & 31;
    int q = blockIdx.x * 8 + warp;
    int b = q >> 12;
    float qx = q_xyz[q * 3 + 0], qy = q_xyz[q * 3 + 1], qz = q_xyz[q * 3 + 2];
    float qn = qx * qx + qy * qy + qz * qz;

    float d8[8]; int i8[8];
#pragma unroll
    for (int i = 0; i < 8; i++) { d8[i] = INF; i8[i] = -1; }
    float worst = INF;

    for (int t0 = 0; t0 < M_; t0 += TILE_) {
        __syncthreads();
        for (int t = threadIdx.x; t < TILE_; t += blockDim.x) {
            size_t j = (size_t)b * M_ + t0 + t;
            float x = kv_xyz[j * 3 + 0];
            float y = kv_xyz[j * 3 + 1];
            float z = kv_xyz[j * 3 + 2];
            sx[t] = x; sy[t] = y; sz[t] = z;
            sn[t] = kv_pad[j] ? INF : (x * x + y * y + z * z);
        }
        __syncthreads();
        for (int t = lane; t < TILE_; t += 32) {
            float d2 = qn + sn[t] - 2.f * (qx * sx[t] + qy * sy[t] + qz * sz[t]);
            if (d2 <= 0.04f && d2 < worst) {
                int p = 7;
                while (p > 0 && d8[p - 1] > d2) { d8[p] = d8[p - 1]; i8[p] = i8[p - 1]; p--; }
                d8[p] = d2; i8[p] = t0 + t;
                worst = d8[7];
            }
        }
    }
    int p = 0;
    for (int r = 0; r < 8; r++) {
        float dv = (p < 8) ? d8[p] : INF;
        int   iv = (p < 8) ? i8[p] : 0;
        unsigned db = __float_as_uint(fmaxf(dv, 0.f));
        unsigned long long key = ((unsigned long long)db << 32)
                               | ((unsigned)(iv & 0x1FFF) << 5) | (unsigned)lane;
#pragma unroll
        for (int o = 16; o; o >>= 1) {
            unsigned long long other = __shfl_xor_sync(0xffffffffu, key, o);
            key = (other < key) ? other : key;
        }
        bool valid = ((unsigned)(key >> 32)) < 0x7f800000u;
        int wlane  = (int)(key & 31u);
        if (valid && lane == wlane) p++;
        if (lane == 0) nidx[q * 8 + r] = valid ? (int)((key >> 5) & 0x1FFF) : -1;
    }
}

// ================= gather attention (fp32 in, bf16 out) =========================
__global__ void attn_kernel(const float* __restrict__ Qq,
                            const float* __restrict__ Kq,
                            const float* __restrict__ Vq,
                            const float* __restrict__ Kkv,
                            const float* __restrict__ Vkv,
                            const int* __restrict__ nidx,
                            __nv_bfloat16* __restrict__ O) {
    int warp = threadIdx.x >> 5, lane = threadIdx.x & 31;
    int q = blockIdx.x * 8 + warp;
    int b = q >> 12;
    const size_t off = (size_t)q * C_ + lane * 8;

    float4 qa = *(const float4*)&Qq[off];
    float4 qb = *(const float4*)&Qq[off + 4];
    float qr[8] = {qa.x, qa.y, qa.z, qa.w, qb.x, qb.y, qb.z, qb.w};

    int rid[8]; int nt = 1;
#pragma unroll
    for (int j = 0; j < 8; j++) {
        rid[j] = nidx[q * 8 + j];
        if (rid[j] >= 0) nt++;
    }
    float sc[9];
#pragma unroll
    for (int j = 0; j < 9; j++) {
        if (j == 0 || j < nt) {
            const float* kr = (j == 0) ? &Kq[off]
                : &Kkv[((size_t)b * M_ + rid[j - 1]) * C_ + lane * 8];
            float4 ka = *(const float4*)kr;
            float4 kb = *(const float4*)(kr + 4);
            float s = qr[0] * ka.x + qr[1] * ka.y + qr[2] * ka.z + qr[3] * ka.w
                    + qr[4] * kb.x + qr[5] * kb.y + qr[6] * kb.z + qr[7] * kb.w;
            s += __shfl_xor_sync(0xffffffffu, s, 1);
            s += __shfl_xor_sync(0xffffffffu, s, 2);
            sc[j] = s * 0.17677669529663687f;
        } else sc[j] = -__int_as_float(0x7f800000);
    }
    float m = sc[0];
#pragma unroll
    for (int j = 1; j < 9; j++) m = fmaxf(m, sc[j]);
    float w[9], ssum = 0.f;
#pragma unroll
    for (int j = 0; j < 9; j++) {
        w[j] = (j == 0 || j < nt) ? expf(sc[j] - m) : 0.f;
        ssum += w[j];
    }
    float inv = 1.f / ssum;

    float o[8] = {0, 0, 0, 0, 0, 0, 0, 0};
#pragma unroll
    for (int j = 0; j < 9; j++) {
        if (j == 0 || j < nt) {
            const float* vr = (j == 0) ? &Vq[off]
                : &Vkv[((size_t)b * M_ + rid[j - 1]) * C_ + lane * 8];
            float4 va = *(const float4*)vr;
            float4 vb = *(const float4*)(vr + 4);
            float a = w[j] * inv;
            o[0] += a * va.x; o[1] += a * va.y; o[2] += a * va.z; o[3] += a * va.w;
            o[4] += a * vb.x; o[5] += a * vb.y; o[6] += a * vb.z; o[7] += a * vb.w;
        }
    }
    __nv_bfloat162 pk[4];
#pragma unroll
    for (int t = 0; t < 4; t++) pk[t] = __floats2bfloat162_rn(o[2 * t], o[2 * t + 1]);
    *(uint4*)&O[off] = *(uint4*)pk;
}

// ================= residual + LayerNorm ========================================
__global__ void ln_res_kernel(const float* __restrict__ A,
                              const float* __restrict__ Bv,
                              const float* __restrict__ g,
                              const float* __restrict__ be,
                              const float* __restrict__ addq,
                              float* __restrict__ out,
                              __nv_bfloat16* __restrict__ outb) {
    int warp = threadIdx.x >> 5, lane = threadIdx.x & 31;
    int row = blockIdx.x * 8 + warp;
    size_t off = (size_t)row * C_ + lane * 8;

    float v[8];
    float4 a0 = *(const float4*)&A[off],  a1 = *(const float4*)&A[off + 4];
    float4 b0 = *(const float4*)&Bv[off], b1 = *(const float4*)&Bv[off + 4];
    v[0] = a0.x + b0.x; v[1] = a0.y + b0.y; v[2] = a0.z + b0.z; v[3] = a0.w + b0.w;
    v[4] = a1.x + b1.x; v[5] = a1.y + b1.y; v[6] = a1.z + b1.z; v[7] = a1.w + b1.w;

    float s = 0.f;
#pragma unroll
    for (int d = 0; d < 8; d++) s += v[d];
#pragma unroll
    for (int o = 16; o; o >>= 1) s += __shfl_xor_sync(0xffffffffu, s, o);
    float mu = s * (1.f / 256.f);
    float s2 = 0.f;
#pragma unroll
    for (int d = 0; d < 8; d++) { float t = v[d] - mu; s2 += t * t; }
#pragma unroll
    for (int o = 16; o; o >>= 1) s2 += __shfl_xor_sync(0xffffffffu, s2, o);
    float is = rsqrtf(s2 * (1.f / 256.f) + 1e-5f);

    float r[8];
#pragma unroll
    for (int d = 0; d < 8; d++) {
        r[d] = (v[d] - mu) * is * g[lane * 8 + d] + be[lane * 8 + d];
        if (addq) r[d] += addq[off + d];
    }
    if (out) {
        float4 r0 = {r[0], r[1], r[2], r[3]}, r1 = {r[4], r[5], r[6], r[7]};
        *(float4*)&out[off] = r0;
        *(float4*)&out[off + 4] = r1;
    }
    if (outb) {
        __nv_bfloat162 pk[4];
#pragma unroll
        for (int t = 0; t < 4; t++) pk[t] = __floats2bfloat162_rn(r[2 * t], r[2 * t + 1]);
        *(uint4*)&outb[off] = *(uint4*)pk;
    }
}

// ================= launch =======================================================
extern "C" void kernel_launch(void* const* d_in, const int* in_sizes, int n_in,
                              void* d_out, int out_size) {
    (void)in_sizes; (void)n_in; (void)out_size;
    const float* q_xyz   = (const float*)d_in[0];
    const float* q_feat  = (const float*)d_in[1];
    const float* kv_xyz  = (const float*)d_in[2];
    const float* kv_feat = (const float*)d_in[3];
    const unsigned char* kv_pad = (const unsigned char*)d_in[4];
    const float* Wpos  = (const float*)d_in[5];
    const float* bpos  = (const float*)d_in[6];
    const float* Wq    = (const float*)d_in[7];
    const float* bq    = (const float*)d_in[8];
    const float* Wk    = (const float*)d_in[9];
    const float* bk    = (const float*)d_in[10];
    const float* Wv    = (const float*)d_in[11];
    const float* bv    = (const float*)d_in[12];
    const float* Wo    = (const float*)d_in[13];
    const float* bo    = (const float*)d_in[14];
    const float* ln1_g = (const float*)d_in[15];
    const float* ln1_b = (const float*)d_in[16];
    const float* W1    = (const float*)d_in[17];
    const float* b1    = (const float*)d_in[18];
    const float* W2    = (const float*)d_in[19];
    const float* b2    = (const float*)d_in[20];
    const float* ln2_g = (const float*)d_in[21];
    const float* ln2_b = (const float*)d_in[22];
    float* out = (float*)d_out;

    float *Xq, *Qq, *Kq, *Vq, *Kkv, *Vkv, *Y;
    __nv_bfloat16 *Xqb, *Xkvb, *Ob, *Yb, *Hidb, *WTq, *WTk, *WTv, *WTo, *WT1, *WT2;
    int* nidx;
    cudaGetSymbolAddress((void**)&Xq,   g_Xq);
    cudaGetSymbolAddress((void**)&Xqb,  g_Xq_b);
    cudaGetSymbolAddress((void**)&Xkvb, g_Xkv_b);
    cudaGetSymbolAddress((void**)&Qq,   g_Qq);
    cudaGetSymbolAddress((void**)&Kq,   g_Kq);
    cudaGetSymbolAddress((void**)&Vq,   g_Vq);
    cudaGetSymbolAddress((void**)&Kkv,  g_Kkv);
    cudaGetSymbolAddress((void**)&Vkv,  g_Vkv);
    cudaGetSymbolAddress((void**)&Ob,   g_O_b);
    cudaGetSymbolAddress((void**)&Y,    g_Y);
    cudaGetSymbolAddress((void**)&Yb,   g_Y_b);
    cudaGetSymbolAddress((void**)&Hidb, g_Hid_b);
    cudaGetSymbolAddress((void**)&nidx, g_nidx);
    cudaGetSymbolAddress((void**)&WTq,  g_WTq);
    cudaGetSymbolAddress((void**)&WTk,  g_WTk);
    cudaGetSymbolAddress((void**)&WTv,  g_WTv);
    cudaGetSymbolAddress((void**)&WTo,  g_WTo);
    cudaGetSymbolAddress((void**)&WT1,  g_WT1);
    cudaGetSymbolAddress((void**)&WT2,  g_WT2);

    // weight transposes -> bf16 [N,K]
    transpose_w<<<(C_ * C_) / 256, 256>>>(Wq, WTq, C_, C_);
    transpose_w<<<(C_ * C_) / 256, 256>>>(Wk, WTk, C_, C_);
    transpose_w<<<(C_ * C_) / 256, 256>>>(Wv, WTv, C_, C_);
    transpose_w<<<(C_ * C_) / 256, 256>>>(Wo, WTo, C_, C_);
    transpose_w<<<(C_ * FF_) / 256, 256>>>(W1, WT1, C_, FF_);
    transpose_w<<<(FF_ * C_) / 256, 256>>>(W2, WT2, FF_, C_);

    // token embeddings
    posenc_kernel<<<NQ_, 256>>>(q_xyz,  q_feat,  Wpos, bpos, Xq, Xqb);
    posenc_kernel<<<NM_, 256>>>(kv_xyz, kv_feat, Wpos, bpos, nullptr, Xkvb);

    // radius-kNN
    knn_kernel<<<NQ_ / 8, 256>>>(q_xyz, kv_xyz, kv_pad, nidx);

    // projections (HMMA tensor cores)
    dim3 gq(C_ / 128, NQ_ / 128);
    dim3 gkv(C_ / 128, NM_ / 128);
    gemm_hmma<0><<<gq,  256>>>(Xqb,  WTq, bq, Qq,  C_, C_);
    gemm_hmma<0><<<gq,  256>>>(Xqb,  WTk, bk, Kq,  C_, C_);
    gemm_hmma<0><<<gq,  256>>>(Xqb,  WTv, bv, Vq,  C_, C_);
    gemm_hmma<0><<<gkv, 256>>>(Xkvb, WTk, bk, Kkv, C_, C_);
    gemm_hmma<0><<<gkv, 256>>>(Xkvb, WTv, bv, Vkv, C_, C_);

    // attention (token-0 row only)
    attn_kernel<<<NQ_ / 8, 256>>>(Qq, Kq, Vq, Kkv, Vkv, nidx, Ob);

    // output projection (reuse Qq as O2), residual + LN1
    gemm_hmma<0><<<gq, 256>>>(Ob, WTo, bo, Qq, C_, C_);
    ln_res_kernel<<<NQ_ / 8, 256>>>(Xq, Qq, ln1_g, ln1_b, nullptr, Y, Yb);

    // FFN
    dim3 g3(FF_ / 128, NQ_ / 128);
    gemm_hmma<1><<<g3, 256>>>(Yb, WT1, b1, Hidb, C_, FF_);
    gemm_hmma<0><<<gq, 256>>>(Hidb, WT2, b2, Kq, FF_, C_);  // FFN2 -> reuse Kq

    // residual + LN2 + final q_feat add, straight into d_out
    ln_res_kernel<<<NQ_ / 8, 256>>>(Y, Kq, ln2_g, ln2_b, q_feat, out, nullptr);
}

// round 4
// speedup vs baseline: 4.4481x; 2.4406x over previous
#include <cuda_runtime.h>
#include <cuda_bf16.h>
#include <math.h>
#include <cstdint>

#define B_   4
#define N_   4096
#define M_   8192
#define C_   256
#define K_   8
#define FF_  1024
#define NQ_  (B_ * N_)   /* 16384 query tokens  */
#define NM_  (B_ * M_)   /* 32768 kv tokens     */
#define NCELL_ (B_ * 125)

// ================= scratch (allocation-free, __device__ globals) ================
__device__ float          g_Xq   [NQ_ * C_];
__device__ __nv_bfloat16  g_Xq_b [NQ_ * C_];
__device__ __nv_bfloat16  g_Xkv_b[NM_ * C_];
__device__ __nv_bfloat16  g_QKVq [NQ_ * 3 * C_];   // [N,768]: Q|K|V
__device__ __nv_bfloat16  g_KVkv [NM_ * 2 * C_];   // [M,512]: K|V
__device__ __nv_bfloat16  g_O_b  [NQ_ * C_];
__device__ float          g_T32  [NQ_ * C_];       // Wo out, later FFN2 out
__device__ float          g_Y    [NQ_ * C_];
__device__ __nv_bfloat16  g_Y_b  [NQ_ * C_];
__device__ __nv_bfloat16  g_Hid_b[NQ_ * FF_];
__device__ int            g_nidx [NQ_ * K_];
// binned kNN structures
__device__ int            g_cnt  [NCELL_];
__device__ int            g_cnt2 [NCELL_];
__device__ int            g_start[NCELL_];
__device__ float4         g_pts  [NM_];
__device__ int            g_pidx [NM_];
// prepped weights (bf16, [N,K] layout) + concat biases
__device__ __nv_bfloat16  g_WTqkv[3 * C_ * C_];
__device__ __nv_bfloat16  g_WTkv [2 * C_ * C_];
__device__ __nv_bfloat16  g_WTo  [C_ * C_];
__device__ __nv_bfloat16  g_WT1  [FF_ * C_];
__device__ __nv_bfloat16  g_WT2  [C_ * FF_];
__device__ float          g_bqkv [3 * C_];
__device__ float          g_bkv  [2 * C_];

__device__ __forceinline__ uint32_t smem_u32(const void* p) {
    uint32_t a;
    asm("{ .reg .u64 t; cvta.to.shared.u64 t, %1; cvt.u32.u64 %0, t; }" : "=r"(a) : "l"(p));
    return a;
}

// ================= fused weight prep (one launch) ===============================
// 787712 flat work items: Wq, Wk(x2 dest), Wv(x2 dest), Wo, W1, W2, bqkv, bkv
__global__ void prep_weights(const float* __restrict__ Wq, const float* __restrict__ Wk,
                             const float* __restrict__ Wv, const float* __restrict__ Wo,
                             const float* __restrict__ W1, const float* __restrict__ W2,
                             const float* __restrict__ bq, const float* __restrict__ bk,
                             const float* __restrict__ bv) {
    int idx = blockIdx.x * 256 + threadIdx.x;
    const int S = C_ * C_;                 // 65536
    if (idx < S) {                         // Wq -> WTqkv rows [0,256)
        int k = idx >> 8, n = idx & 255;
        g_WTqkv[(size_t)n * C_ + k] = __float2bfloat16(Wq[idx]);
    } else if (idx < 2 * S) {              // Wk -> WTqkv rows [256,512) + WTkv [0,256)
        int j = idx - S; int k = j >> 8, n = j & 255;
        __nv_bfloat16 v = __float2bfloat16(Wk[j]);
        g_WTqkv[(size_t)(C_ + n) * C_ + k] = v;
        g_WTkv [(size_t)n * C_ + k] = v;
    } else if (idx < 3 * S) {              // Wv -> WTqkv rows [512,768) + WTkv [256,512)
        int j = idx - 2 * S; int k = j >> 8, n = j & 255;
        __nv_bfloat16 v = __float2bfloat16(Wv[j]);
        g_WTqkv[(size_t)(2 * C_ + n) * C_ + k] = v;
        g_WTkv [(size_t)(C_ + n) * C_ + k] = v;
    } else if (idx < 4 * S) {              // Wo
        int j = idx - 3 * S; int k = j >> 8, n = j & 255;
        g_WTo[(size_t)n * C_ + k] = __float2bfloat16(Wo[j]);
    } else if (idx < 4 * S + C_ * FF_) {   // W1 [256,1024]
        int j = idx - 4 * S; int k = j >> 10, n = j & 1023;
        g_WT1[(size_t)n * C_ + k] = __float2bfloat16(W1[j]);
    } else if (idx < 4 * S + 2 * C_ * FF_) { // W2 [1024,256]
        int j = idx - 4 * S - C_ * FF_; int k = j >> 8, n = j & 255;
        g_WT2[(size_t)n * FF_ + k] = __float2bfloat16(W2[j]);
    } else if (idx < 4 * S + 2 * C_ * FF_ + 768) { // bqkv
        int j = idx - 4 * S - 2 * C_ * FF_;
        g_bqkv[j] = (j < 256) ? bq[j] : (j < 512 ? bk[j - 256] : bv[j - 512]);
    } else if (idx < 4 * S + 2 * C_ * FF_ + 768 + 512) { // bkv
        int j = idx - 4 * S - 2 * C_ * FF_ - 768;
        g_bkv[j] = (j < 256) ? bk[j] : bv[j - 256];
    }
}

// ================= pos-encoding ================================================
__global__ void posenc_kernel(const float* __restrict__ xyz,
                              const float* __restrict__ feat,
                              const float* __restrict__ Wpos,
                              const float* __restrict__ bpos,
                              float* __restrict__ Xf,
                              __nv_bfloat16* __restrict__ Xb) {
    int row = blockIdx.x;
    int c   = threadIdx.x;
    float x = xyz[row * 3 + 0], y = xyz[row * 3 + 1], z = xyz[row * 3 + 2];
    float v = feat[(size_t)row * C_ + c]
            + x * Wpos[c] + y * Wpos[C_ + c] + z * Wpos[2 * C_ + c] + bpos[c];
    if (Xf) Xf[(size_t)row * C_ + c] = v;
    Xb[(size_t)row * C_ + c] = __float2bfloat16(v);
}

// ================= HMMA GEMM: Out = A(bf16,[M,K]) @ BT(bf16,[N,K])^T + bias =====
// MODE 0: fp32 out.  MODE 1: relu+bf16 out.  MODE 2: bf16 out.
#define SSTR 40

__device__ __forceinline__ void ldm_x4(uint32_t* r, uint32_t addr) {
    asm volatile("ldmatrix.sync.aligned.m8n8.x4.shared.b16 {%0,%1,%2,%3}, [%4];"
                 : "=r"(r[0]), "=r"(r[1]), "=r"(r[2]), "=r"(r[3]) : "r"(addr));
}
__device__ __forceinline__ void mma_bf16(float* d, const uint32_t* a, const uint32_t* b) {
    asm volatile(
        "mma.sync.aligned.m16n8k16.row.col.f32.bf16.bf16.f32 "
        "{%0,%1,%2,%3}, {%4,%5,%6,%7}, {%8,%9}, {%0,%1,%2,%3};"
        : "+f"(d[0]), "+f"(d[1]), "+f"(d[2]), "+f"(d[3])
        : "r"(a[0]), "r"(a[1]), "r"(a[2]), "r"(a[3]), "r"(b[0]), "r"(b[1]));
}
__device__ __forceinline__ void cp16(uint32_t saddr, const void* gaddr) {
    asm volatile("cp.async.cg.shared.global [%0], [%1], 16;" :: "r"(saddr), "l"(gaddr));
}

template <int MODE>
__global__ __launch_bounds__(256)
void gemm_hmma(const __nv_bfloat16* __restrict__ A,
               const __nv_bfloat16* __restrict__ BT,
               const float* __restrict__ bias,
               void* __restrict__ Out, int K, int N) {
    __shared__ __align__(16) __nv_bfloat16 sA[2][128 * SSTR];
    __shared__ __align__(16) __nv_bfloat16 sB[2][128 * SSTR];

    int tid  = threadIdx.x;
    int wid  = tid >> 5, lane = tid & 31;
    int row0 = blockIdx.y * 128;
    int col0 = blockIdx.x * 128;
    int wm   = (wid & 1) * 64;
    int wn   = (wid >> 1) * 32;

    uint32_t aA[2] = { smem_u32(&sA[0][0]), smem_u32(&sA[1][0]) };
    uint32_t aB[2] = { smem_u32(&sB[0][0]), smem_u32(&sB[1][0]) };

    int r0i = tid >> 2, s0 = (tid & 3) * 8;
    int r1i = (tid + 256) >> 2, s1 = ((tid + 256) & 3) * 8;

    auto issue = [&](int buf, int kc0) {
        cp16(aA[buf] + (r0i * SSTR + s0) * 2, A  + (size_t)(row0 + r0i) * K + kc0 + s0);
        cp16(aA[buf] + (r1i * SSTR + s1) * 2, A  + (size_t)(row0 + r1i) * K + kc0 + s1);
        cp16(aB[buf] + (r0i * SSTR + s0) * 2, BT + (size_t)(col0 + r0i) * K + kc0 + s0);
        cp16(aB[buf] + (r1i * SSTR + s1) * 2, BT + (size_t)(col0 + r1i) * K + kc0 + s1);
        asm volatile("cp.async.commit_group;" ::: "memory");
    };

    float acc[4][4][4] = {};

    int nk = K >> 5;
    issue(0, 0);
    for (int i = 0; i < nk; i++) {
        if (i + 1 < nk) {
            issue((i + 1) & 1, (i + 1) << 5);
            asm volatile("cp.async.wait_group 1;" ::: "memory");
        } else {
            asm volatile("cp.async.wait_group 0;" ::: "memory");
        }
        __syncthreads();

        int buf = i & 1;
#pragma unroll
        for (int ks = 0; ks < 2; ks++) {
            uint32_t afr[4][4];
#pragma unroll
            for (int mt = 0; mt < 4; mt++) {
                uint32_t addr = aA[buf]
                    + ((wm + mt * 16 + (lane & 15)) * SSTR
                       + ks * 16 + ((lane >> 4) << 3)) * 2;
                ldm_x4(afr[mt], addr);
            }
            uint32_t bfr[2][4];
#pragma unroll
            for (int np = 0; np < 2; np++) {
                uint32_t row = wn + np * 16 + ((lane >> 4) << 3) + (lane & 7);
                uint32_t kc  = ks * 16 + ((lane >> 3) & 1) * 8;
                ldm_x4(bfr[np], aB[buf] + (row * SSTR + kc) * 2);
            }
#pragma unroll
            for (int mt = 0; mt < 4; mt++)
#pragma unroll
                for (int nt = 0; nt < 4; nt++)
                    mma_bf16(acc[mt][nt], afr[mt], &bfr[nt >> 1][(nt & 1) * 2]);
        }
        __syncthreads();
    }

    int g  = lane >> 2;
    int t2 = (lane & 3) * 2;
#pragma unroll
    for (int mt = 0; mt < 4; mt++) {
#pragma unroll
        for (int nt = 0; nt < 4; nt++) {
            int row = row0 + wm + mt * 16 + g;
            int col = col0 + wn + nt * 8 + t2;
            float2 b2 = *(const float2*)&bias[col];
            float v0 = acc[mt][nt][0] + b2.x, v1 = acc[mt][nt][1] + b2.y;
            float v2 = acc[mt][nt][2] + b2.x, v3 = acc[mt][nt][3] + b2.y;
            if (MODE == 0) {
                float* op = (float*)Out;
                *(float2*)&op[(size_t)row * N + col]       = make_float2(v0, v1);
                *(float2*)&op[(size_t)(row + 8) * N + col] = make_float2(v2, v3);
            } else {
                if (MODE == 1) {
                    v0 = fmaxf(v0, 0.f); v1 = fmaxf(v1, 0.f);
                    v2 = fmaxf(v2, 0.f); v3 = fmaxf(v3, 0.f);
                }
                __nv_bfloat16* op = (__nv_bfloat16*)Out;
                *(__nv_bfloat162*)&op[(size_t)row * N + col]       = __floats2bfloat162_rn(v0, v1);
                *(__nv_bfloat162*)&op[(size_t)(row + 8) * N + col] = __floats2bfloat162_rn(v2, v3);
            }
        }
    }
}

// ================= binned radius-kNN ============================================
__global__ void zero_cells() {
    int t = threadIdx.x;
    if (t < NCELL_) { g_cnt[t] = 0; g_cnt2[t] = 0; }
}

__device__ __forceinline__ int cell_of(float x, float y, float z) {
    int cx = min((int)(x * 5.f), 4);
    int cy = min((int)(y * 5.f), 4);
    int cz = min((int)(z * 5.f), 4);
    return (cx * 5 + cy) * 5 + cz;
}

__global__ void count_cells(const float* __restrict__ kv_xyz,
                            const unsigned char* __restrict__ kv_pad) {
    int i = blockIdx.x * 256 + threadIdx.x;
    if (i >= NM_ || kv_pad[i]) return;
    int b = i >> 13;
    float x = kv_xyz[i * 3], y = kv_xyz[i * 3 + 1], z = kv_xyz[i * 3 + 2];
    atomicAdd(&g_cnt[b * 125 + cell_of(x, y, z)], 1);
}

__global__ void scan_cells() {
    __shared__ int s[512];
    int t = threadIdx.x;
    int v = (t < NCELL_) ? g_cnt[t] : 0;
    s[t] = v; __syncthreads();
    for (int o = 1; o < 512; o <<= 1) {
        int u = (t >= o) ? s[t - o] : 0;
        __syncthreads();
        s[t] += u;
        __syncthreads();
    }
    if (t < NCELL_) g_start[t] = s[t] - v;
}

__global__ void scatter_cells(const float* __restrict__ kv_xyz,
                              const unsigned char* __restrict__ kv_pad) {
    int i = blockIdx.x * 256 + threadIdx.x;
    if (i >= NM_ || kv_pad[i]) return;
    int b = i >> 13;
    float x = kv_xyz[i * 3], y = kv_xyz[i * 3 + 1], z = kv_xyz[i * 3 + 2];
    int cid = b * 125 + cell_of(x, y, z);
    int pos = g_start[cid] + atomicAdd(&g_cnt2[cid], 1);
    g_pts[pos] = make_float4(x, y, z, x * x + y * y + z * z);
    g_pidx[pos] = i & 8191;
}

// warp per query; scan the 27 neighbor cells only
__global__ void knn_kernel(const float* __restrict__ q_xyz,
                           int* __restrict__ nidx) {
    const float INF = __int_as_float(0x7f800000);
    int warp = threadIdx.x >> 5, lane = threadIdx.x & 31;
    int q = blockIdx.x * 8 + warp;
    int b = q >> 12;
    float qx = q_xyz[q * 3 + 0], qy = q_xyz[q * 3 + 1], qz = q_xyz[q * 3 + 2];
    float qn = qx * qx + qy * qy + qz * qz;
    int cx = min((int)(qx * 5.f), 4);
    int cy = min((int)(qy * 5.f), 4);
    int cz = min((int)(qz * 5.f), 4);

    float d8[8]; int i8[8];
#pragma unroll
    for (int i = 0; i < 8; i++) { d8[i] = INF; i8[i] = -1; }
    float worst = INF;

    for (int dx = -1; dx <= 1; dx++) {
        int x = cx + dx; if (x < 0 || x > 4) continue;
        for (int dy = -1; dy <= 1; dy++) {
            int y = cy + dy; if (y < 0 || y > 4) continue;
            for (int dz = -1; dz <= 1; dz++) {
                int z = cz + dz; if (z < 0 || z > 4) continue;
                int cid = b * 125 + (x * 5 + y) * 5 + z;
                int s0 = g_start[cid], n = g_cnt[cid];
                for (int t = lane; t < n; t += 32) {
                    float4 p = g_pts[s0 + t];
                    float d2 = qn + p.w - 2.f * (qx * p.x + qy * p.y + qz * p.z);
                    if (d2 <= 0.04f && d2 < worst) {
                        int ii = g_pidx[s0 + t];
                        int pp = 7;
                        while (pp > 0 && d8[pp - 1] > d2) {
                            d8[pp] = d8[pp - 1]; i8[pp] = i8[pp - 1]; pp--;
                        }
                        d8[pp] = d2; i8[pp] = ii;
                        worst = d8[7];
                    }
                }
            }
        }
    }

    int p = 0;
    for (int r = 0; r < 8; r++) {
        float dv = (p < 8) ? d8[p] : INF;
        int   iv = (p < 8) ? i8[p] : 0;
        unsigned db = __float_as_uint(fmaxf(dv, 0.f));
        unsigned long long key = ((unsigned long long)db << 32)
                               | ((unsigned)(iv & 0x1FFF) << 5) | (unsigned)lane;
#pragma unroll
        for (int o = 16; o; o >>= 1) {
            unsigned long long other = __shfl_xor_sync(0xffffffffu, key, o);
            key = (other < key) ? other : key;
        }
        bool valid = ((unsigned)(key >> 32)) < 0x7f800000u;
        int wlane  = (int)(key & 31u);
        if (valid && lane == wlane) p++;
        if (lane == 0) nidx[q * 8 + r] = valid ? (int)((key >> 5) & 0x1FFF) : -1;
    }
}

// ================= gather attention (bf16 in, bf16 out) =========================
__device__ __forceinline__ void ld8bf(const __nv_bfloat16* p, float* f) {
    uint4 u = *(const uint4*)p;
    const __nv_bfloat162* h = (const __nv_bfloat162*)&u;
#pragma unroll
    for (int i = 0; i < 4; i++) {
        float2 t = __bfloat1622float2(h[i]);
        f[2 * i] = t.x; f[2 * i + 1] = t.y;
    }
}

__global__ void attn_kernel(const __nv_bfloat16* __restrict__ QKV,
                            const __nv_bfloat16* __restrict__ KV,
                            const int* __restrict__ nidx,
                            __nv_bfloat16* __restrict__ O) {
    int warp = threadIdx.x >> 5, lane = threadIdx.x & 31;
    int q = blockIdx.x * 8 + warp;
    int b = q >> 12;
    const int off8 = lane * 8;
    const __nv_bfloat16* qkv = QKV + (size_t)q * 768;

    float qr[8];
    ld8bf(qkv + off8, qr);

    int rid[8]; int nt = 1;
#pragma unroll
    for (int j = 0; j < 8; j++) {
        rid[j] = nidx[q * 8 + j];
        if (rid[j] >= 0) nt++;
    }
    float sc[9];
#pragma unroll
    for (int j = 0; j < 9; j++) {
        if (j == 0 || j < nt) {
            const __nv_bfloat16* kr = (j == 0)
                ? qkv + 256 + off8
                : KV + ((size_t)b * M_ + rid[j - 1]) * 512 + off8;
            float kf[8];
            ld8bf(kr, kf);
            float s = qr[0] * kf[0] + qr[1] * kf[1] + qr[2] * kf[2] + qr[3] * kf[3]
                    + qr[4] * kf[4] + qr[5] * kf[5] + qr[6] * kf[6] + qr[7] * kf[7];
            s += __shfl_xor_sync(0xffffffffu, s, 1);
            s += __shfl_xor_sync(0xffffffffu, s, 2);
            sc[j] = s * 0.17677669529663687f;
        } else sc[j] = -__int_as_float(0x7f800000);
    }
    float m = sc[0];
#pragma unroll
    for (int j = 1; j < 9; j++) m = fmaxf(m, sc[j]);
    float w[9], ssum = 0.f;
#pragma unroll
    for (int j = 0; j < 9; j++) {
        w[j] = (j == 0 || j < nt) ? expf(sc[j] - m) : 0.f;
        ssum += w[j];
    }
    float inv = 1.f / ssum;

    float o[8] = {0, 0, 0, 0, 0, 0, 0, 0};
#pragma unroll
    for (int j = 0; j < 9; j++) {
        if (j == 0 || j < nt) {
            const __nv_bfloat16* vr = (j == 0)
                ? qkv + 512 + off8
                : KV + ((size_t)b * M_ + rid[j - 1]) * 512 + 256 + off8;
            float vf[8];
            ld8bf(vr, vf);
            float a = w[j] * inv;
#pragma unroll
            for (int d = 0; d < 8; d++) o[d] += a * vf[d];
        }
    }
    __nv_bfloat162 pk[4];
#pragma unroll
    for (int t = 0; t < 4; t++) pk[t] = __floats2bfloat162_rn(o[2 * t], o[2 * t + 1]);
    *(uint4*)&O[(size_t)q * C_ + off8] = *(uint4*)pk;
}

// ================= residual + LayerNorm ========================================
__global__ void ln_res_kernel(const float* __restrict__ A,
                              const float* __restrict__ Bv,
                              const float* __restrict__ g,
                              const float* __restrict__ be,
                              const float* __restrict__ addq,
                              float* __restrict__ out,
                              __nv_bfloat16* __restrict__ outb) {
    int warp = threadIdx.x >> 5, lane = threadIdx.x & 31;
    int row = blockIdx.x * 8 + warp;
    size_t off = (size_t)row * C_ + lane * 8;

    float v[8];
    float4 a0 = *(const float4*)&A[off],  a1 = *(const float4*)&A[off + 4];
    float4 b0 = *(const float4*)&Bv[off], b1 = *(const float4*)&Bv[off + 4];
    v[0] = a0.x + b0.x; v[1] = a0.y + b0.y; v[2] = a0.z + b0.z; v[3] = a0.w + b0.w;
    v[4] = a1.x + b1.x; v[5] = a1.y + b1.y; v[6] = a1.z + b1.z; v[7] = a1.w + b1.w;

    float s = 0.f;
#pragma unroll
    for (int d = 0; d < 8; d++) s += v[d];
#pragma unroll
    for (int o = 16; o; o >>= 1) s += __shfl_xor_sync(0xffffffffu, s, o);
    float mu = s * (1.f / 256.f);
    float s2 = 0.f;
#pragma unroll
    for (int d = 0; d < 8; d++) { float t = v[d] - mu; s2 += t * t; }
#pragma unroll
    for (int o = 16; o; o >>= 1) s2 += __shfl_xor_sync(0xffffffffu, s2, o);
    float is = rsqrtf(s2 * (1.f / 256.f) + 1e-5f);

    float r[8];
#pragma unroll
    for (int d = 0; d < 8; d++) {
        r[d] = (v[d] - mu) * is * g[lane * 8 + d] + be[lane * 8 + d];
        if (addq) r[d] += addq[off + d];
    }
    if (out) {
        *(float4*)&out[off]     = make_float4(r[0], r[1], r[2], r[3]);
        *(float4*)&out[off + 4] = make_float4(r[4], r[5], r[6], r[7]);
    }
    if (outb) {
        __nv_bfloat162 pk[4];
#pragma unroll
        for (int t = 0; t < 4; t++) pk[t] = __floats2bfloat162_rn(r[2 * t], r[2 * t + 1]);
        *(uint4*)&outb[off] = *(uint4*)pk;
    }
}

// ================= launch =======================================================
extern "C" void kernel_launch(void* const* d_in, const int* in_sizes, int n_in,
                              void* d_out, int out_size) {
    (void)in_sizes; (void)n_in; (void)out_size;
    const float* q_xyz   = (const float*)d_in[0];
    const float* q_feat  = (const float*)d_in[1];
    const float* kv_xyz  = (const float*)d_in[2];
    const float* kv_feat = (const float*)d_in[3];
    const unsigned char* kv_pad = (const unsigned char*)d_in[4];
    const float* Wpos  = (const float*)d_in[5];
    const float* bpos  = (const float*)d_in[6];
    const float* Wq    = (const float*)d_in[7];
    const float* bq    = (const float*)d_in[8];
    const float* Wk    = (const float*)d_in[9];
    const float* bk    = (const float*)d_in[10];
    const float* Wv    = (const float*)d_in[11];
    const float* bv    = (const float*)d_in[12];
    const float* Wo    = (const float*)d_in[13];
    const float* bo    = (const float*)d_in[14];
    const float* ln1_g = (const float*)d_in[15];
    const float* ln1_b = (const float*)d_in[16];
    const float* W1    = (const float*)d_in[17];
    const float* b1    = (const float*)d_in[18];
    const float* W2    = (const float*)d_in[19];
    const float* b2    = (const float*)d_in[20];
    const float* ln2_g = (const float*)d_in[21];
    const float* ln2_b = (const float*)d_in[22];
    float* out = (float*)d_out;

    float *Xq, *T32, *Y, *bqkv, *bkv;
    __nv_bfloat16 *Xqb, *Xkvb, *QKVq, *KVkv, *Ob, *Yb, *Hidb, *WTqkv, *WTkv, *WTo, *WT1, *WT2;
    int* nidx;
    cudaGetSymbolAddress((void**)&Xq,    g_Xq);
    cudaGetSymbolAddress((void**)&Xqb,   g_Xq_b);
    cudaGetSymbolAddress((void**)&Xkvb,  g_Xkv_b);
    cudaGetSymbolAddress((void**)&QKVq,  g_QKVq);
    cudaGetSymbolAddress((void**)&KVkv,  g_KVkv);
    cudaGetSymbolAddress((void**)&Ob,    g_O_b);
    cudaGetSymbolAddress((void**)&T32,   g_T32);
    cudaGetSymbolAddress((void**)&Y,     g_Y);
    cudaGetSymbolAddress((void**)&Yb,    g_Y_b);
    cudaGetSymbolAddress((void**)&Hidb,  g_Hid_b);
    cudaGetSymbolAddress((void**)&nidx,  g_nidx);
    cudaGetSymbolAddress((void**)&WTqkv, g_WTqkv);
    cudaGetSymbolAddress((void**)&WTkv,  g_WTkv);
    cudaGetSymbolAddress((void**)&WTo,   g_WTo);
    cudaGetSymbolAddress((void**)&WT1,   g_WT1);
    cudaGetSymbolAddress((void**)&WT2,   g_WT2);
    cudaGetSymbolAddress((void**)&bqkv,  g_bqkv);
    cudaGetSymbolAddress((void**)&bkv,   g_bkv);

    // 0: weight prep (single fused launch)
    prep_weights<<<3077, 256>>>(Wq, Wk, Wv, Wo, W1, W2, bq, bk, bv);
    // 1-2: token embeddings
    posenc_kernel<<<NQ_, 256>>>(q_xyz,  q_feat,  Wpos, bpos, Xq, Xqb);
    posenc_kernel<<<NM_, 256>>>(kv_xyz, kv_feat, Wpos, bpos, nullptr, Xkvb);
    // 3-4: knn binning (part 1)
    zero_cells<<<1, 512>>>();
    count_cells<<<NM_ / 256, 256>>>(kv_xyz, kv_pad);
    // 5: fused QKV projection (profiled slot)
    dim3 gqkv(768 / 128, NQ_ / 128);
    gemm_hmma<2><<<gqkv, 256>>>(Xqb, WTqkv, bqkv, QKVq, C_, 768);
    // 6-8: knn binning (part 2) + query
    scan_cells<<<1, 512>>>();
    scatter_cells<<<NM_ / 256, 256>>>(kv_xyz, kv_pad);
    knn_kernel<<<NQ_ / 8, 256>>>(q_xyz, nidx);
    // 9: fused KV projection
    dim3 gkv(512 / 128, NM_ / 128);
    gemm_hmma<2><<<gkv, 256>>>(Xkvb, WTkv, bkv, KVkv, C_, 512);
    // 10: gather attention
    attn_kernel<<<NQ_ / 8, 256>>>(QKVq, KVkv, nidx, Ob);
    // 11-12: output projection + LN1
    dim3 go(C_ / 128, NQ_ / 128);
    gemm_hmma<0><<<go, 256>>>(Ob, WTo, bo, T32, C_, C_);
    ln_res_kernel<<<NQ_ / 8, 256>>>(Xq, T32, ln1_g, ln1_b, nullptr, Y, Yb);
    // 13-14: FFN
    dim3 gf1(FF_ / 128, NQ_ / 128);
    gemm_hmma<1><<<gf1, 256>>>(Yb, WT1, b1, Hidb, C_, FF_);
    gemm_hmma<0><<<go, 256>>>(Hidb, WT2, b2, T32, FF_, C_);
    // 15: LN2 + residual + q_feat, straight into d_out
    ln_res_kernel<<<NQ_ / 8, 256>>>(Y, T32, ln2_g, ln2_b, q_feat, out, nullptr);
}

// round 5
// speedup vs baseline: 4.6516x; 1.0458x over previous
#include <cuda_runtime.h>
#include <cuda_bf16.h>
#include <math.h>
#include <cstdint>

#define B_   4
#define N_   4096
#define M_   8192
#define C_   256
#define K_   8
#define FF_  1024
#define NQ_  (B_ * N_)
#define NM_  (B_ * M_)
#define NCELL_ (B_ * 125)

// ================= scratch ======================================================
__device__ float          g_Xq   [NQ_ * C_];
__device__ __nv_bfloat16  g_Xq_b [NQ_ * C_];
__device__ __nv_bfloat16  g_Xkv_b[NM_ * C_];
__device__ __nv_bfloat16  g_QKVq [NQ_ * 3 * C_];
__device__ __nv_bfloat16  g_KVkv [NM_ * 2 * C_];
__device__ __nv_bfloat16  g_O_b  [NQ_ * C_];
__device__ float          g_T32  [NQ_ * C_];
__device__ float          g_Y    [NQ_ * C_];
__device__ __nv_bfloat16  g_Y_b  [NQ_ * C_];
__device__ __nv_bfloat16  g_Hid_b[NQ_ * FF_];
__device__ int            g_nidx [NQ_ * K_];
__device__ int            g_cnt  [NCELL_];
__device__ int            g_cnt2 [NCELL_];
__device__ int            g_start[NCELL_];
__device__ float4         g_pts  [NM_];
__device__ int            g_pidx [NM_];
__device__ __nv_bfloat16  g_WTqkv[3 * C_ * C_];
__device__ __nv_bfloat16  g_WTkv [2 * C_ * C_];
__device__ __nv_bfloat16  g_WTo  [C_ * C_];
__device__ __nv_bfloat16  g_WT1  [FF_ * C_];
__device__ __nv_bfloat16  g_WT2  [C_ * FF_];
__device__ float          g_bqkv [3 * C_];
__device__ float          g_bkv  [2 * C_];

__device__ __forceinline__ uint32_t smem_u32(const void* p) {
    uint32_t a;
    asm("{ .reg .u64 t; cvta.to.shared.u64 t, %1; cvt.u32.u64 %0, t; }" : "=r"(a) : "l"(p));
    return a;
}

// ================= fused weight prep + cell zeroing (one launch) ================
__global__ void prep_weights(const float* __restrict__ Wq, const float* __restrict__ Wk,
                             const float* __restrict__ Wv, const float* __restrict__ Wo,
                             const float* __restrict__ W1, const float* __restrict__ W2,
                             const float* __restrict__ bq, const float* __restrict__ bk,
                             const float* __restrict__ bv) {
    int idx = blockIdx.x * 256 + threadIdx.x;
    const int S = C_ * C_;
    const int E0 = 4 * S + 2 * C_ * FF_;          // 786432
    if (idx < S) {
        int k = idx >> 8, n = idx & 255;
        g_WTqkv[(size_t)n * C_ + k] = __float2bfloat16(Wq[idx]);
    } else if (idx < 2 * S) {
        int j = idx - S; int k = j >> 8, n = j & 255;
        __nv_bfloat16 v = __float2bfloat16(Wk[j]);
        g_WTqkv[(size_t)(C_ + n) * C_ + k] = v;
        g_WTkv [(size_t)n * C_ + k] = v;
    } else if (idx < 3 * S) {
        int j = idx - 2 * S; int k = j >> 8, n = j & 255;
        __nv_bfloat16 v = __float2bfloat16(Wv[j]);
        g_WTqkv[(size_t)(2 * C_ + n) * C_ + k] = v;
        g_WTkv [(size_t)(C_ + n) * C_ + k] = v;
    } else if (idx < 4 * S) {
        int j = idx - 3 * S; int k = j >> 8, n = j & 255;
        g_WTo[(size_t)n * C_ + k] = __float2bfloat16(Wo[j]);
    } else if (idx < 4 * S + C_ * FF_) {
        int j = idx - 4 * S; int k = j >> 10, n = j & 1023;
        g_WT1[(size_t)n * C_ + k] = __float2bfloat16(W1[j]);
    } else if (idx < E0) {
        int j = idx - 4 * S - C_ * FF_; int k = j >> 8, n = j & 255;
        g_WT2[(size_t)n * FF_ + k] = __float2bfloat16(W2[j]);
    } else if (idx < E0 + 768) {
        int j = idx - E0;
        g_bqkv[j] = (j < 256) ? bq[j] : (j < 512 ? bk[j - 256] : bv[j - 512]);
    } else if (idx < E0 + 768 + 512) {
        int j = idx - E0 - 768;
        g_bkv[j] = (j < 256) ? bk[j] : bv[j - 256];
    } else if (idx < E0 + 768 + 512 + NCELL_) {
        int j = idx - E0 - 768 - 512;
        g_cnt[j] = 0; g_cnt2[j] = 0;
    }
}
#define PREP_ITEMS (4 * C_ * C_ + 2 * C_ * FF_ + 768 + 512 + NCELL_)

// ================= fused pos-encoding (q + kv in one launch) ====================
__global__ void posenc_kernel(const float* __restrict__ q_xyz,
                              const float* __restrict__ q_feat,
                              const float* __restrict__ kv_xyz,
                              const float* __restrict__ kv_feat,
                              const float* __restrict__ Wpos,
                              const float* __restrict__ bpos) {
    int row = blockIdx.x;
    int c   = threadIdx.x;
    const float* xyz; const float* feat;
    if (row < NQ_) { xyz = q_xyz + row * 3; feat = q_feat + (size_t)row * C_; }
    else { int r = row - NQ_; xyz = kv_xyz + r * 3; feat = kv_feat + (size_t)r * C_; }
    float x = xyz[0], y = xyz[1], z = xyz[2];
    float v = feat[c] + x * Wpos[c] + y * Wpos[C_ + c] + z * Wpos[2 * C_ + c] + bpos[c];
    if (row < NQ_) {
        g_Xq[(size_t)row * C_ + c] = v;
        g_Xq_b[(size_t)row * C_ + c] = __float2bfloat16(v);
    } else {
        g_Xkv_b[(size_t)(row - NQ_) * C_ + c] = __float2bfloat16(v);
    }
}

// ================= HMMA GEMM (3-stage cp.async pipeline) ========================
// MODE 0: fp32 out.  MODE 1: relu+bf16 out.  MODE 2: bf16 out.
#define SSTR 40
#define STG_BYTES (128 * SSTR * 2)      /* 10240 B per operand per stage */
#define GEMM_SMEM (3 * STG_BYTES * 2)   /* 61440 B */

__device__ __forceinline__ void ldm_x4(uint32_t* r, uint32_t addr) {
    asm volatile("ldmatrix.sync.aligned.m8n8.x4.shared.b16 {%0,%1,%2,%3}, [%4];"
                 : "=r"(r[0]), "=r"(r[1]), "=r"(r[2]), "=r"(r[3]) : "r"(addr));
}
__device__ __forceinline__ void mma_bf16(float* d, const uint32_t* a, const uint32_t* b) {
    asm volatile(
        "mma.sync.aligned.m16n8k16.row.col.f32.bf16.bf16.f32 "
        "{%0,%1,%2,%3}, {%4,%5,%6,%7}, {%8,%9}, {%0,%1,%2,%3};"
        : "+f"(d[0]), "+f"(d[1]), "+f"(d[2]), "+f"(d[3])
        : "r"(a[0]), "r"(a[1]), "r"(a[2]), "r"(a[3]), "r"(b[0]), "r"(b[1]));
}
__device__ __forceinline__ void cp16(uint32_t saddr, const void* gaddr) {
    asm volatile("cp.async.cg.shared.global [%0], [%1], 16;" :: "r"(saddr), "l"(gaddr));
}

template <int MODE>
__global__ __launch_bounds__(256, 2)
void gemm_hmma(const __nv_bfloat16* __restrict__ A,
               const __nv_bfloat16* __restrict__ BT,
               const float* __restrict__ bias,
               void* __restrict__ Out, int K, int N) {
    extern __shared__ char dsm[];
    int tid  = threadIdx.x;
    int wid  = tid >> 5, lane = tid & 31;
    int row0 = blockIdx.y * 128;
    int col0 = blockIdx.x * 128;
    int wm   = (wid & 1) * 64;
    int wn   = (wid >> 1) * 32;

    uint32_t aA = smem_u32(dsm);
    uint32_t aB = aA + 3 * STG_BYTES;

    int r0i = tid >> 2, s0 = (tid & 3) * 8;
    int r1i = (tid + 256) >> 2, s1 = ((tid + 256) & 3) * 8;

    auto issue = [&](int st, int kc0) {
        uint32_t oA = aA + st * STG_BYTES, oB = aB + st * STG_BYTES;
        cp16(oA + (r0i * SSTR + s0) * 2, A  + (size_t)(row0 + r0i) * K + kc0 + s0);
        cp16(oA + (r1i * SSTR + s1) * 2, A  + (size_t)(row0 + r1i) * K + kc0 + s1);
        cp16(oB + (r0i * SSTR + s0) * 2, BT + (size_t)(col0 + r0i) * K + kc0 + s0);
        cp16(oB + (r1i * SSTR + s1) * 2, BT + (size_t)(col0 + r1i) * K + kc0 + s1);
        asm volatile("cp.async.commit_group;" ::: "memory");
    };

    float acc[4][4][4] = {};
    int nk = K >> 5;

    issue(0, 0);
    issue(1, 32);

    for (int i = 0; i < nk; i++) {
        if (i < nk - 1) asm volatile("cp.async.wait_group 1;" ::: "memory");
        else            asm volatile("cp.async.wait_group 0;" ::: "memory");
        __syncthreads();

        if (i + 2 < nk) issue((i + 2) % 3, (i + 2) << 5);

        uint32_t bA = aA + (i % 3) * STG_BYTES;
        uint32_t bB = aB + (i % 3) * STG_BYTES;
#pragma unroll
        for (int ks = 0; ks < 2; ks++) {
            uint32_t afr[4][4];
#pragma unroll
            for (int mt = 0; mt < 4; mt++) {
                uint32_t addr = bA + ((wm + mt * 16 + (lane & 15)) * SSTR
                                      + ks * 16 + ((lane >> 4) << 3)) * 2;
                ldm_x4(afr[mt], addr);
            }
            uint32_t bfr[2][4];
#pragma unroll
            for (int np = 0; np < 2; np++) {
                uint32_t row = wn + np * 16 + ((lane >> 4) << 3) + (lane & 7);
                uint32_t kc  = ks * 16 + ((lane >> 3) & 1) * 8;
                ldm_x4(bfr[np], bB + (row * SSTR + kc) * 2);
            }
#pragma unroll
            for (int mt = 0; mt < 4; mt++)
#pragma unroll
                for (int nt = 0; nt < 4; nt++)
                    mma_bf16(acc[mt][nt], afr[mt], &bfr[nt >> 1][(nt & 1) * 2]);
        }
        __syncthreads();
    }

    int g  = lane >> 2;
    int t2 = (lane & 3) * 2;
#pragma unroll
    for (int mt = 0; mt < 4; mt++) {
#pragma unroll
        for (int nt = 0; nt < 4; nt++) {
            int row = row0 + wm + mt * 16 + g;
            int col = col0 + wn + nt * 8 + t2;
            float2 b2 = *(const float2*)&bias[col];
            float v0 = acc[mt][nt][0] + b2.x, v1 = acc[mt][nt][1] + b2.y;
            float v2 = acc[mt][nt][2] + b2.x, v3 = acc[mt][nt][3] + b2.y;
            if (MODE == 0) {
                float* op = (float*)Out;
                *(float2*)&op[(size_t)row * N + col]       = make_float2(v0, v1);
                *(float2*)&op[(size_t)(row + 8) * N + col] = make_float2(v2, v3);
            } else {
                if (MODE == 1) {
                    v0 = fmaxf(v0, 0.f); v1 = fmaxf(v1, 0.f);
                    v2 = fmaxf(v2, 0.f); v3 = fmaxf(v3, 0.f);
                }
                __nv_bfloat16* op = (__nv_bfloat16*)Out;
                *(__nv_bfloat162*)&op[(size_t)row * N + col]       = __floats2bfloat162_rn(v0, v1);
                *(__nv_bfloat162*)&op[(size_t)(row + 8) * N + col] = __floats2bfloat162_rn(v2, v3);
            }
        }
    }
}

// ================= binned radius-kNN ============================================
__device__ __forceinline__ int cell_of(float x, float y, float z) {
    int cx = min((int)(x * 5.f), 4);
    int cy = min((int)(y * 5.f), 4);
    int cz = min((int)(z * 5.f), 4);
    return (cx * 5 + cy) * 5 + cz;
}

__global__ void count_cells(const float* __restrict__ kv_xyz,
                            const unsigned char* __restrict__ kv_pad) {
    int i = blockIdx.x * 256 + threadIdx.x;
    if (i >= NM_ || kv_pad[i]) return;
    int b = i >> 13;
    float x = kv_xyz[i * 3], y = kv_xyz[i * 3 + 1], z = kv_xyz[i * 3 + 2];
    atomicAdd(&g_cnt[b * 125 + cell_of(x, y, z)], 1);
}

__global__ void scan_cells() {
    __shared__ int s[512];
    int t = threadIdx.x;
    int v = (t < NCELL_) ? g_cnt[t] : 0;
    s[t] = v; __syncthreads();
    for (int o = 1; o < 512; o <<= 1) {
        int u = (t >= o) ? s[t - o] : 0;
        __syncthreads();
        s[t] += u;
        __syncthreads();
    }
    if (t < NCELL_) g_start[t] = s[t] - v;
}

__global__ void scatter_cells(const float* __restrict__ kv_xyz,
                              const unsigned char* __restrict__ kv_pad) {
    int i = blockIdx.x * 256 + threadIdx.x;
    if (i >= NM_ || kv_pad[i]) return;
    int b = i >> 13;
    float x = kv_xyz[i * 3], y = kv_xyz[i * 3 + 1], z = kv_xyz[i * 3 + 2];
    int cid = b * 125 + cell_of(x, y, z);
    int pos = g_start[cid] + atomicAdd(&g_cnt2[cid], 1);
    g_pts[pos] = make_float4(x, y, z, x * x + y * y + z * z);
    g_pidx[pos] = i & 8191;
}

__global__ void knn_kernel(const float* __restrict__ q_xyz,
                           int* __restrict__ nidx) {
    const float INF = __int_as_float(0x7f800000);
    int warp = threadIdx.x >> 5, lane = threadIdx.x & 31;
    int q = blockIdx.x * 8 + warp;
    int b = q >> 12;
    float qx = q_xyz[q * 3 + 0], qy = q_xyz[q * 3 + 1], qz = q_xyz[q * 3 + 2];
    float qn = qx * qx + qy * qy + qz * qz;
    int cx = min((int)(qx * 5.f), 4);
    int cy = min((int)(qy * 5.f), 4);
    int cz = min((int)(qz * 5.f), 4);

    float d8[8]; int i8[8];
#pragma unroll
    for (int i = 0; i < 8; i++) { d8[i] = INF; i8[i] = -1; }
    float worst = INF;

    for (int dx = -1; dx <= 1; dx++) {
        int x = cx + dx; if (x < 0 || x > 4) continue;
        for (int dy = -1; dy <= 1; dy++) {
            int y = cy + dy; if (y < 0 || y > 4) continue;
            for (int dz = -1; dz <= 1; dz++) {
                int z = cz + dz; if (z < 0 || z > 4) continue;
                int cid = b * 125 + (x * 5 + y) * 5 + z;
                int s0 = g_start[cid], n = g_cnt[cid];
                for (int t = lane; t < n; t += 32) {
                    float4 p = g_pts[s0 + t];
                    float d2 = qn + p.w - 2.f * (qx * p.x + qy * p.y + qz * p.z);
                    if (d2 <= 0.04f && d2 < worst) {
                        int ii = g_pidx[s0 + t];
                        int pp = 7;
                        while (pp > 0 && d8[pp - 1] > d2) {
                            d8[pp] = d8[pp - 1]; i8[pp] = i8[pp - 1]; pp--;
                        }
                        d8[pp] = d2; i8[pp] = ii;
                        worst = d8[7];
                    }
                }
            }
        }
    }

    int p = 0;
    for (int r = 0; r < 8; r++) {
        float dv = (p < 8) ? d8[p] : INF;
        int   iv = (p < 8) ? i8[p] : 0;
        unsigned db = __float_as_uint(fmaxf(dv, 0.f));
        unsigned long long key = ((unsigned long long)db << 32)
                               | ((unsigned)(iv & 0x1FFF) << 5) | (unsigned)lane;
#pragma unroll
        for (int o = 16; o; o >>= 1) {
            unsigned long long other = __shfl_xor_sync(0xffffffffu, key, o);
            key = (other < key) ? other : key;
        }
        bool valid = ((unsigned)(key >> 32)) < 0x7f800000u;
        int wlane  = (int)(key & 31u);
        if (valid && lane == wlane) p++;
        if (lane == 0) nidx[q * 8 + r] = valid ? (int)((key >> 5) & 0x1FFF) : -1;
    }
}

// ================= gather attention =============================================
__device__ __forceinline__ void ld8bf(const __nv_bfloat16* p, float* f) {
    uint4 u = *(const uint4*)p;
    const __nv_bfloat162* h = (const __nv_bfloat162*)&u;
#pragma unroll
    for (int i = 0; i < 4; i++) {
        float2 t = __bfloat1622float2(h[i]);
        f[2 * i] = t.x; f[2 * i + 1] = t.y;
    }
}

__global__ void attn_kernel(const __nv_bfloat16* __restrict__ QKV,
                            const __nv_bfloat16* __restrict__ KV,
                            const int* __restrict__ nidx,
                            __nv_bfloat16* __restrict__ O) {
    int warp = threadIdx.x >> 5, lane = threadIdx.x & 31;
    int q = blockIdx.x * 8 + warp;
    int b = q >> 12;
    const int off8 = lane * 8;
    const __nv_bfloat16* qkv = QKV + (size_t)q * 768;

    float qr[8];
    ld8bf(qkv + off8, qr);

    int rid[8]; int nt = 1;
#pragma unroll
    for (int j = 0; j < 8; j++) {
        rid[j] = nidx[q * 8 + j];
        if (rid[j] >= 0) nt++;
    }
    float sc[9];
#pragma unroll
    for (int j = 0; j < 9; j++) {
        if (j == 0 || j < nt) {
            const __nv_bfloat16* kr = (j == 0)
                ? qkv + 256 + off8
                : KV + ((size_t)b * M_ + rid[j - 1]) * 512 + off8;
            float kf[8];
            ld8bf(kr, kf);
            float s = qr[0] * kf[0] + qr[1] * kf[1] + qr[2] * kf[2] + qr[3] * kf[3]
                    + qr[4] * kf[4] + qr[5] * kf[5] + qr[6] * kf[6] + qr[7] * kf[7];
            s += __shfl_xor_sync(0xffffffffu, s, 1);
            s += __shfl_xor_sync(0xffffffffu, s, 2);
            sc[j] = s * 0.17677669529663687f;
        } else sc[j] = -__int_as_float(0x7f800000);
    }
    float m = sc[0];
#pragma unroll
    for (int j = 1; j < 9; j++) m = fmaxf(m, sc[j]);
    float w[9], ssum = 0.f;
#pragma unroll
    for (int j = 0; j < 9; j++) {
        w[j] = (j == 0 || j < nt) ? expf(sc[j] - m) : 0.f;
        ssum += w[j];
    }
    float inv = 1.f / ssum;

    float o[8] = {0, 0, 0, 0, 0, 0, 0, 0};
#pragma unroll
    for (int j = 0; j < 9; j++) {
        if (j == 0 || j < nt) {
            const __nv_bfloat16* vr = (j == 0)
                ? qkv + 512 + off8
                : KV + ((size_t)b * M_ + rid[j - 1]) * 512 + 256 + off8;
            float vf[8];
            ld8bf(vr, vf);
            float a = w[j] * inv;
#pragma unroll
            for (int d = 0; d < 8; d++) o[d] += a * vf[d];
        }
    }
    __nv_bfloat162 pk[4];
#pragma unroll
    for (int t = 0; t < 4; t++) pk[t] = __floats2bfloat162_rn(o[2 * t], o[2 * t + 1]);
    *(uint4*)&O[(size_t)q * C_ + off8] = *(uint4*)pk;
}

// ================= residual + LayerNorm ========================================
__global__ void ln_res_kernel(const float* __restrict__ A,
                              const float* __restrict__ Bv,
                              const float* __restrict__ g,
                              const float* __restrict__ be,
                              const float* __restrict__ addq,
                              float* __restrict__ out,
                              __nv_bfloat16* __restrict__ outb) {
    int warp = threadIdx.x >> 5, lane = threadIdx.x & 31;
    int row = blockIdx.x * 8 + warp;
    size_t off = (size_t)row * C_ + lane * 8;

    float v[8];
    float4 a0 = *(const float4*)&A[off],  a1 = *(const float4*)&A[off + 4];
    float4 b0 = *(const float4*)&Bv[off], b1 = *(const float4*)&Bv[off + 4];
    v[0] = a0.x + b0.x; v[1] = a0.y + b0.y; v[2] = a0.z + b0.z; v[3] = a0.w + b0.w;
    v[4] = a1.x + b1.x; v[5] = a1.y + b1.y; v[6] = a1.z + b1.z; v[7] = a1.w + b1.w;

    float s = 0.f;
#pragma unroll
    for (int d = 0; d < 8; d++) s += v[d];
#pragma unroll
    for (int o = 16; o; o >>= 1) s += __shfl_xor_sync(0xffffffffu, s, o);
    float mu = s * (1.f / 256.f);
    float s2 = 0.f;
#pragma unroll
    for (int d = 0; d < 8; d++) { float t = v[d] - mu; s2 += t * t; }
#pragma unroll
    for (int o = 16; o; o >>= 1) s2 += __shfl_xor_sync(0xffffffffu, s2, o);
    float is = rsqrtf(s2 * (1.f / 256.f) + 1e-5f);

    float r[8];
#pragma unroll
    for (int d = 0; d < 8; d++) {
        r[d] = (v[d] - mu) * is * g[lane * 8 + d] + be[lane * 8 + d];
        if (addq) r[d] += addq[off + d];
    }
    if (out) {
        *(float4*)&out[off]     = make_float4(r[0], r[1], r[2], r[3]);
        *(float4*)&out[off + 4] = make_float4(r[4], r[5], r[6], r[7]);
    }
    if (outb) {
        __nv_bfloat162 pk[4];
#pragma unroll
        for (int t = 0; t < 4; t++) pk[t] = __floats2bfloat162_rn(r[2 * t], r[2 * t + 1]);
        *(uint4*)&outb[off] = *(uint4*)pk;
    }
}

// ================= launch =======================================================
extern "C" void kernel_launch(void* const* d_in, const int* in_sizes, int n_in,
                              void* d_out, int out_size) {
    (void)in_sizes; (void)n_in; (void)out_size;
    const float* q_xyz   = (const float*)d_in[0];
    const float* q_feat  = (const float*)d_in[1];
    const float* kv_xyz  = (const float*)d_in[2];
    const float* kv_feat = (const float*)d_in[3];
    const unsigned char* kv_pad = (const unsigned char*)d_in[4];
    const float* Wpos  = (const float*)d_in[5];
    const float* bpos  = (const float*)d_in[6];
    const float* Wq    = (const float*)d_in[7];
    const float* bq    = (const float*)d_in[8];
    const float* Wk    = (const float*)d_in[9];
    const float* bk    = (const float*)d_in[10];
    const float* Wv    = (const float*)d_in[11];
    const float* bv    = (const float*)d_in[12];
    const float* Wo    = (const float*)d_in[13];
    const float* bo    = (const float*)d_in[14];
    const float* ln1_g = (const float*)d_in[15];
    const float* ln1_b = (const float*)d_in[16];
    const float* W1    = (const float*)d_in[17];
    const float* b1    = (const float*)d_in[18];
    const float* W2    = (const float*)d_in[19];
    const float* b2    = (const float*)d_in[20];
    const float* ln2_g = (const float*)d_in[21];
    const float* ln2_b = (const float*)d_in[22];
    float* out = (float*)d_out;

    float *Xq, *T32, *Y, *bqkv, *bkv;
    __nv_bfloat16 *Xqb, *Xkvb, *QKVq, *KVkv, *Ob, *Yb, *Hidb, *WTqkv, *WTkv, *WTo, *WT1, *WT2;
    int* nidx;
    cudaGetSymbolAddress((void**)&Xq,    g_Xq);
    cudaGetSymbolAddress((void**)&Xqb,   g_Xq_b);
    cudaGetSymbolAddress((void**)&Xkvb,  g_Xkv_b);
    cudaGetSymbolAddress((void**)&QKVq,  g_QKVq);
    cudaGetSymbolAddress((void**)&KVkv,  g_KVkv);
    cudaGetSymbolAddress((void**)&Ob,    g_O_b);
    cudaGetSymbolAddress((void**)&T32,   g_T32);
    cudaGetSymbolAddress((void**)&Y,     g_Y);
    cudaGetSymbolAddress((void**)&Yb,    g_Y_b);
    cudaGetSymbolAddress((void**)&Hidb,  g_Hid_b);
    cudaGetSymbolAddress((void**)&nidx,  g_nidx);
    cudaGetSymbolAddress((void**)&WTqkv, g_WTqkv);
    cudaGetSymbolAddress((void**)&WTkv,  g_WTkv);
    cudaGetSymbolAddress((void**)&WTo,   g_WTo);
    cudaGetSymbolAddress((void**)&WT1,   g_WT1);
    cudaGetSymbolAddress((void**)&WT2,   g_WT2);
    cudaGetSymbolAddress((void**)&bqkv,  g_bqkv);
    cudaGetSymbolAddress((void**)&bkv,   g_bkv);

    cudaFuncSetAttribute(gemm_hmma<0>, cudaFuncAttributeMaxDynamicSharedMemorySize, GEMM_SMEM);
    cudaFuncSetAttribute(gemm_hmma<1>, cudaFuncAttributeMaxDynamicSharedMemorySize, GEMM_SMEM);
    cudaFuncSetAttribute(gemm_hmma<2>, cudaFuncAttributeMaxDynamicSharedMemorySize, GEMM_SMEM);

    // 0: weight prep + cell zeroing
    prep_weights<<<(PREP_ITEMS + 255) / 256, 256>>>(Wq, Wk, Wv, Wo, W1, W2, bq, bk, bv);
    // 1: fused pos-encoding
    posenc_kernel<<<NQ_ + NM_, 256>>>(q_xyz, q_feat, kv_xyz, kv_feat, Wpos, bpos);
    // 2: cell counts
    count_cells<<<NM_ / 256, 256>>>(kv_xyz, kv_pad);
    // 3: fused QKV projection  <-- profiled slot
    dim3 gqkv(768 / 128, NQ_ / 128);
    gemm_hmma<2><<<gqkv, 256, GEMM_SMEM>>>(Xqb, WTqkv, bqkv, QKVq, C_, 768);
    // 4-6: knn
    scan_cells<<<1, 512>>>();
    scatter_cells<<<NM_ / 256, 256>>>(kv_xyz, kv_pad);
    knn_kernel<<<NQ_ / 8, 256>>>(q_xyz, nidx);
    // 7: fused KV projection
    dim3 gkv(512 / 128, NM_ / 128);
    gemm_hmma<2><<<gkv, 256, GEMM_SMEM>>>(Xkvb, WTkv, bkv, KVkv, C_, 512);
    // 8: gather attention
    attn_kernel<<<NQ_ / 8, 256>>>(QKVq, KVkv, nidx, Ob);
    // 9-10: output projection + LN1
    dim3 go(C_ / 128, NQ_ / 128);
    gemm_hmma<0><<<go, 256, GEMM_SMEM>>>(Ob, WTo, bo, T32, C_, C_);
    ln_res_kernel<<<NQ_ / 8, 256>>>(Xq, T32, ln1_g, ln1_b, nullptr, Y, Yb);
    // 11-12: FFN
    dim3 gf1(FF_ / 128, NQ_ / 128);
    gemm_hmma<1><<<gf1, 256, GEMM_SMEM>>>(Yb, WT1, b1, Hidb, C_, FF_);
    gemm_hmma<0><<<go, 256, GEMM_SMEM>>>(Hidb, WT2, b2, T32, FF_, C_);
    // 13: LN2 + residual + q_feat -> d_out
    ln_res_kernel<<<NQ_ / 8, 256>>>(Y, T32, ln2_g, ln2_b, q_feat, out, nullptr);
}